// round 1
// baseline (speedup 1.0000x reference)
#include <cuda_runtime.h>
#include <cuda_bf16.h>
#include <math.h>

// Problem constants
#define B_    2
#define T_    2048
#define V_    32000
#define DM    1024
#define DI_   2048
#define NS    16
#define RR    64
#define LL    4
#define KK    4
#define MTOK  (B_*T_)   // 4096

// ---------------- scratch (device globals; no allocation allowed) ----------
__device__ float g_x   [MTOK*DM];        // residual stream
__device__ float g_h   [MTOK*DM];        // layernorm output
__device__ float g_xz  [MTOK*2*DI_];     // in_proj output (x_in | z)
__device__ float g_xc  [MTOK*DI_];       // conv+silu output
__device__ float g_proj[MTOK*96];        // x_proj output (dt_r | B | C)
__device__ float g_dt  [MTOK*DI_];       // softplus dt
__device__ float g_y   [MTOK*DI_];       // scan output * silu(z)

// ---------------- helpers ---------------------------------------------------
__device__ __forceinline__ float softplusf(float x) {
    return x > 20.f ? x : log1pf(expf(x));
}
__device__ __forceinline__ float siluf(float x) {
    return x / (1.f + __expf(-x));
}

// ---------------- embed -----------------------------------------------------
__global__ void embed_kernel(const int* __restrict__ ids,
                             const float* __restrict__ E,
                             float* __restrict__ x) {
    int i = blockIdx.x * blockDim.x + threadIdx.x;   // over MTOK*DM
    if (i >= MTOK * DM) return;
    int row = i >> 10;        // /DM
    int d   = i & (DM - 1);
    x[i] = E[(size_t)ids[row] * DM + d];
}

// ---------------- layernorm (one block per row, 256 thr, 4 floats each) -----
__global__ __launch_bounds__(256) void ln_kernel(const float* __restrict__ x,
                                                 const float* __restrict__ w,
                                                 const float* __restrict__ b,
                                                 float* __restrict__ out) {
    int row = blockIdx.x;
    int tid = threadIdx.x;
    const float4* xr = (const float4*)(x + (size_t)row * DM);
    float4 v = xr[tid];
    float s  = v.x + v.y + v.z + v.w;
    float sq = v.x*v.x + v.y*v.y + v.z*v.z + v.w*v.w;
    // warp reduce
    #pragma unroll
    for (int o = 16; o > 0; o >>= 1) {
        s  += __shfl_xor_sync(0xffffffff, s,  o);
        sq += __shfl_xor_sync(0xffffffff, sq, o);
    }
    __shared__ float rs[8], rq[8];
    int warp = tid >> 5, lane = tid & 31;
    if (lane == 0) { rs[warp] = s; rq[warp] = sq; }
    __syncthreads();
    __shared__ float smu, srstd;
    if (tid == 0) {
        float ts = 0.f, tq = 0.f;
        #pragma unroll
        for (int i = 0; i < 8; ++i) { ts += rs[i]; tq += rq[i]; }
        float mu  = ts * (1.f / DM);
        float var = tq * (1.f / DM) - mu * mu;
        smu = mu;
        srstd = rsqrtf(var + 1e-5f);
    }
    __syncthreads();
    float mu = smu, rstd = srstd;
    float4 wv = ((const float4*)w)[tid];
    float4 bv = ((const float4*)b)[tid];
    float4 o;
    o.x = (v.x - mu) * rstd * wv.x + bv.x;
    o.y = (v.y - mu) * rstd * wv.y + bv.y;
    o.z = (v.z - mu) * rstd * wv.z + bv.z;
    o.w = (v.w - mu) * rstd * wv.w + bv.w;
    ((float4*)(out + (size_t)row * DM))[tid] = o;
}

// ---------------- tiled fp32 GEMM: C[m,n] = sum_k A[m,k]*W[n,k] -------------
// A: M x K (row stride lda), W: N x K (row stride ldw), C: M x N (row stride ldc)
// M must be a multiple of 128; N,K arbitrary multiples of (1,16) resp.
// ACT: 0 none, 1 softplus.  BIAS: add bias[n].  ACC: C += existing C (residual).
template<int ACT, bool BIAS, bool ACC>
__global__ __launch_bounds__(256) void gemm_nt(
    int M, int N, int K,
    const float* __restrict__ A, int lda,
    const float* __restrict__ W, int ldw,
    float* __restrict__ C, int ldc,
    const float* __restrict__ bias)
{
    __shared__ float As[16][132];
    __shared__ float Ws[16][132];
    int tid = threadIdx.x;
    int bm = blockIdx.y * 128, bn = blockIdx.x * 128;
    int tx = tid & 15, ty = tid >> 4;
    int lrow = tid >> 2;           // 0..63
    int kq   = (tid & 3) * 4;      // 0,4,8,12

    float acc[8][8];
    #pragma unroll
    for (int i = 0; i < 8; ++i)
        #pragma unroll
        for (int j = 0; j < 8; ++j) acc[i][j] = 0.f;

    for (int k0 = 0; k0 < K; k0 += 16) {
        #pragma unroll
        for (int half = 0; half < 2; ++half) {
            int r = lrow + half * 64;
            float4 v = *(const float4*)(A + (size_t)(bm + r) * lda + k0 + kq);
            As[kq+0][r] = v.x; As[kq+1][r] = v.y;
            As[kq+2][r] = v.z; As[kq+3][r] = v.w;
            int rn = bn + r;
            float4 u;
            if (rn < N) u = *(const float4*)(W + (size_t)rn * ldw + k0 + kq);
            else        u = make_float4(0.f, 0.f, 0.f, 0.f);
            Ws[kq+0][r] = u.x; Ws[kq+1][r] = u.y;
            Ws[kq+2][r] = u.z; Ws[kq+3][r] = u.w;
        }
        __syncthreads();
        #pragma unroll
        for (int k = 0; k < 16; ++k) {
            float a[8], w[8];
            #pragma unroll
            for (int i = 0; i < 8; ++i) a[i] = As[k][ty*8 + i];
            #pragma unroll
            for (int j = 0; j < 8; ++j) w[j] = Ws[k][tx*8 + j];
            #pragma unroll
            for (int i = 0; i < 8; ++i)
                #pragma unroll
                for (int j = 0; j < 8; ++j)
                    acc[i][j] = fmaf(a[i], w[j], acc[i][j]);
        }
        __syncthreads();
    }

    #pragma unroll
    for (int i = 0; i < 8; ++i) {
        int m = bm + ty*8 + i;
        #pragma unroll
        for (int j = 0; j < 8; ++j) {
            int n = bn + tx*8 + j;
            if (n < N) {
                float v = acc[i][j];
                if (BIAS) v += bias[n];
                if (ACC)  v += C[(size_t)m * ldc + n];
                if (ACT == 1) v = softplusf(v);
                C[(size_t)m * ldc + n] = v;
            }
        }
    }
}

// ---------------- causal depthwise conv (K=4) + silu ------------------------
__global__ void conv_silu_kernel(const float* __restrict__ xz,
                                 const float* __restrict__ cw,
                                 const float* __restrict__ cb,
                                 float* __restrict__ xc) {
    int i = blockIdx.x * blockDim.x + threadIdx.x;   // over MTOK*DI_
    if (i >= MTOK * DI_) return;
    int c  = i & (DI_ - 1);
    int bt = i >> 11;                // /DI_
    int t  = bt & (T_ - 1);
    float acc = cb[c];
    #pragma unroll
    for (int k = 0; k < KK; ++k) {
        int tt = t + k - (KK - 1);
        if (tt >= 0)
            acc += xz[(size_t)(bt + k - (KK - 1)) * (2*DI_) + c] * cw[c*KK + k];
    }
    xc[i] = siluf(acc);
}

// ---------------- selective scan + D skip + silu(z) gate --------------------
// One thread per (b, d).  Grid: (DI_/256, B_).  N=16 state in registers.
// Fast path exploits A[n] = -(n+1)  (verified at runtime per-thread): one exp
// per timestep, powers by a log-depth product tree.
__global__ __launch_bounds__(256) void scan_kernel(
    const float* __restrict__ xc,
    const float* __restrict__ dtb,
    const float* __restrict__ proj,
    const float* __restrict__ xz,
    const float* __restrict__ Alog,
    const float* __restrict__ Dp,
    float* __restrict__ y)
{
    int d = blockIdx.x * blockDim.x + threadIdx.x;
    int b = blockIdx.y;
    float A[NS];
    bool fast = true;
    #pragma unroll
    for (int n = 0; n < NS; ++n) {
        A[n] = -expf(Alog[(size_t)d * NS + n]);
        fast = fast && (fabsf(A[n] + (float)(n + 1)) <= 1e-3f * (n + 1));
    }
    float Dv = Dp[d];
    float h[NS];
    #pragma unroll
    for (int n = 0; n < NS; ++n) h[n] = 0.f;

    __shared__ float sBC[64][33];   // 64 timesteps x (16 B | 16 C)

    for (int t0 = 0; t0 < T_; t0 += 64) {
        __syncthreads();
        for (int e = threadIdx.x; e < 64*32; e += blockDim.x) {
            int i = e >> 5, j = e & 31;
            sBC[i][j] = proj[((size_t)b*T_ + t0 + i) * 96 + RR + j];
        }
        __syncthreads();
        for (int i = 0; i < 64; ++i) {
            size_t idx = (size_t)b*T_ + t0 + i;
            float u   = xc [idx * DI_ + d];
            float dtv = dtb[idx * DI_ + d];
            float dA[NS];
            if (fast) {
                float p  = __expf(-dtv);
                float p2 = p*p, p4 = p2*p2, p8 = p4*p4;
                dA[0]=p;        dA[1]=p2;       dA[2]=p2*p;      dA[3]=p4;
                dA[4]=p4*p;     dA[5]=p4*p2;    dA[6]=p4*p2*p;   dA[7]=p8;
                dA[8]=p8*p;     dA[9]=p8*p2;    dA[10]=p8*p2*p;  dA[11]=p8*p4;
                dA[12]=p8*p4*p; dA[13]=p8*p4*p2; dA[14]=p8*p4*p2*p; dA[15]=p8*p8;
            } else {
                #pragma unroll
                for (int n = 0; n < NS; ++n) dA[n] = __expf(dtv * A[n]);
            }
            float du = dtv * u;
            float accv = 0.f;
            #pragma unroll
            for (int n = 0; n < NS; ++n) {
                h[n] = dA[n] * h[n] + du * sBC[i][n];
                accv += h[n] * sBC[i][NS + n];
            }
            float z = xz[idx * (2*DI_) + DI_ + d];
            y[idx * DI_ + d] = (accv + u * Dv) * siluf(z);
        }
    }
}

// ---------------- launch ----------------------------------------------------
extern "C" void kernel_launch(void* const* d_in, const int* in_sizes, int n_in,
                              void* d_out, int out_size) {
    const int*   ids       = (const int*)  d_in[0];
    const float* embed_W   = (const float*)d_in[1];
    const float* out_b     = (const float*)d_in[2];
    const float* ln_w      = (const float*)d_in[3];
    const float* ln_b      = (const float*)d_in[4];
    const float* norm_w    = (const float*)d_in[5];
    const float* norm_b    = (const float*)d_in[6];
    const float* in_proj_W = (const float*)d_in[7];
    const float* conv_W    = (const float*)d_in[8];
    const float* conv_b    = (const float*)d_in[9];
    const float* x_proj_W  = (const float*)d_in[10];
    const float* dt_proj_W = (const float*)d_in[11];
    const float* dt_proj_b = (const float*)d_in[12];
    const float* A_log     = (const float*)d_in[13];
    const float* D_param   = (const float*)d_in[14];
    const float* out_projW = (const float*)d_in[15];
    float* out = (float*)d_out;

    float *px, *ph, *pxz, *pxc, *pproj, *pdt, *py;
    cudaGetSymbolAddress((void**)&px,    g_x);
    cudaGetSymbolAddress((void**)&ph,    g_h);
    cudaGetSymbolAddress((void**)&pxz,   g_xz);
    cudaGetSymbolAddress((void**)&pxc,   g_xc);
    cudaGetSymbolAddress((void**)&pproj, g_proj);
    cudaGetSymbolAddress((void**)&pdt,   g_dt);
    cudaGetSymbolAddress((void**)&py,    g_y);

    embed_kernel<<<(MTOK*DM + 255)/256, 256>>>(ids, embed_W, px);

    for (int l = 0; l < LL; ++l) {
        ln_kernel<<<MTOK, 256>>>(px, norm_w + l*DM, norm_b + l*DM, ph);

        // xz = h @ in_proj^T   (4096 x 4096 x 1024)
        gemm_nt<0,false,false><<<dim3(32, 32), 256>>>(
            MTOK, 2*DI_, DM, ph, DM,
            in_proj_W + (size_t)l*2*DI_*DM, DM, pxz, 2*DI_, nullptr);

        conv_silu_kernel<<<(MTOK*DI_ + 255)/256, 256>>>(
            pxz, conv_W + (size_t)l*DI_*KK, conv_b + (size_t)l*DI_, pxc);

        // proj = xc @ x_proj^T  (4096 x 96 x 2048)
        gemm_nt<0,false,false><<<dim3(1, 32), 256>>>(
            MTOK, 96, DI_, pxc, DI_,
            x_proj_W + (size_t)l*96*DI_, DI_, pproj, 96, nullptr);

        // dt = softplus(dt_r @ dt_proj^T + b)  (4096 x 2048 x 64)
        gemm_nt<1,true,false><<<dim3(16, 32), 256>>>(
            MTOK, DI_, RR, pproj, 96,
            dt_proj_W + (size_t)l*DI_*RR, RR, pdt, DI_,
            dt_proj_b + (size_t)l*DI_);

        scan_kernel<<<dim3(DI_/256, B_), 256>>>(
            pxc, pdt, pproj, pxz,
            A_log + (size_t)l*DI_*NS, D_param + (size_t)l*DI_, py);

        // x += y @ out_proj^T   (4096 x 1024 x 2048), residual accumulate
        gemm_nt<0,false,true><<<dim3(8, 32), 256>>>(
            MTOK, DM, DI_, py, DI_,
            out_projW + (size_t)l*DM*DI_, DI_, px, DM, nullptr);
    }

    ln_kernel<<<MTOK, 256>>>(px, ln_w, ln_b, ph);

    // logits = h @ embed^T + out_b   (4096 x 32000 x 1024)
    gemm_nt<0,true,false><<<dim3((V_ + 127)/128, 32), 256>>>(
        MTOK, V_, DM, ph, DM, embed_W, DM, out, V_, out_b);
}

// round 3
// speedup vs baseline: 1.4191x; 1.4191x over previous
#include <cuda_runtime.h>
#include <cuda_bf16.h>
#include <math.h>
#include <stdint.h>

// Problem constants
#define B_    2
#define T_    2048
#define V_    32000
#define DM    1024
#define DI_   2048
#define NS    16
#define RR    64
#define LL    4
#define KK    4
#define MTOK  (B_*T_)   // 4096

// ---------------- scratch (device globals; no allocation allowed) ----------
__device__ float g_x   [MTOK*DM];
__device__ float g_h   [MTOK*DM];
__device__ float g_xz  [MTOK*2*DI_];
__device__ float g_xc  [MTOK*DI_];
__device__ float g_proj[MTOK*96];
__device__ float g_dt  [MTOK*DI_];
__device__ float g_y   [MTOK*DI_];

// ---------------- helpers ---------------------------------------------------
__device__ __forceinline__ float softplusf(float x) {
    return x > 20.f ? x : log1pf(expf(x));
}
__device__ __forceinline__ float siluf(float x) {
    return x / (1.f + __expf(-x));
}
__device__ __forceinline__ uint32_t smem_u32(const void* p) {
    uint32_t a;
    asm("{ .reg .u64 t; cvta.to.shared.u64 t, %1; cvt.u32.u64 %0, t; }"
        : "=r"(a) : "l"(p));
    return a;
}
__device__ __forceinline__ void ldsm4(uint32_t* r, uint32_t addr) {
    asm volatile("ldmatrix.sync.aligned.m8n8.x4.shared.b16 {%0,%1,%2,%3}, [%4];"
        : "=r"(r[0]), "=r"(r[1]), "=r"(r[2]), "=r"(r[3]) : "r"(addr));
}
__device__ __forceinline__ void mma_bf16(float* d, const uint32_t* a, uint32_t b0, uint32_t b1) {
    asm volatile(
        "mma.sync.aligned.m16n8k16.row.col.f32.bf16.bf16.f32 "
        "{%0,%1,%2,%3}, {%4,%5,%6,%7}, {%8,%9}, {%0,%1,%2,%3};"
        : "+f"(d[0]), "+f"(d[1]), "+f"(d[2]), "+f"(d[3])
        : "r"(a[0]), "r"(a[1]), "r"(a[2]), "r"(a[3]), "r"(b0), "r"(b1));
}

// hi/lo bf16 split of 4 floats, packed as 2x uint2 (memory order preserved)
__device__ __forceinline__ void split4(float4 v, uint2& hi, uint2& lo) {
    float f[4] = {v.x, v.y, v.z, v.w};
    uint32_t h[4], l[4];
    #pragma unroll
    for (int i = 0; i < 4; ++i) {
        __nv_bfloat16 hb = __float2bfloat16_rn(f[i]);
        float rem = f[i] - __bfloat162float(hb);
        __nv_bfloat16 lb = __float2bfloat16_rn(rem);
        h[i] = (uint32_t)__bfloat16_as_ushort(hb);
        l[i] = (uint32_t)__bfloat16_as_ushort(lb);
    }
    hi.x = h[0] | (h[1] << 16); hi.y = h[2] | (h[3] << 16);
    lo.x = l[0] | (l[1] << 16); lo.y = l[2] | (l[3] << 16);
}

// ---------------- HMMA GEMM: C[m,n] = sum_k A[m,k]*W[n,k] -------------------
// bf16 hi/lo compensated (3 mma passes) -> ~fp32 accuracy.
// Block tile 128x128, K-chunks of 32. M % 128 == 0, K % 32 == 0.
// NGUARD: N not a multiple of 128 (guard W loads and C stores).
// Tiles in smem (bf16, row stride 40 elems = 80B): p0=Ah p1=Al p2=Wh p3=Wl
#define TILE_B   10240           // bytes per tile (128*40*2)
#define GSMEM    (4*TILE_B)      // 40KB

template<int ACT, bool BIAS, bool ACC, bool NGUARD>
__global__ __launch_bounds__(256) void gemm_hmma(
    int M, int N, int K,
    const float* __restrict__ A, int lda,
    const float* __restrict__ W, int ldw,
    float* __restrict__ C, int ldc,
    const float* __restrict__ bias)
{
    extern __shared__ char sm[];
    int tid = threadIdx.x;
    int lane = tid & 31, wid = tid >> 5;
    int warp_m = wid >> 2, warp_n = wid & 3;
    int bm = blockIdx.x * 128, bn = blockIdx.y * 128;
    int NC = K >> 5;

    // per-lane ldmatrix address components
    int a_row = warp_m * 64 + (lane & 15);
    int a_col = (lane >> 4) * 8;
    int b_row = warp_n * 32 + (lane & 7) + ((lane >> 4) << 3);
    int b_col = ((lane >> 3) & 1) * 8;
    uint32_t smb = smem_u32(sm);

    float acc[4][4][4];
    #pragma unroll
    for (int i = 0; i < 4; ++i)
        #pragma unroll
        for (int j = 0; j < 4; ++j)
            #pragma unroll
            for (int q = 0; q < 4; ++q) acc[i][j][q] = 0.f;

    float4 pa[4], pw[4];
    // load a chunk's A/W fp32 into registers
    auto loadG = [&](int k0) {
        #pragma unroll
        for (int it = 0; it < 4; ++it) {
            int idx = it * 256 + tid;
            int row = idx >> 3, c4 = idx & 7;
            pa[it] = *(const float4*)(A + (size_t)(bm + row) * lda + k0 + c4 * 4);
            int rn = bn + row;
            if (NGUARD && rn >= N) pw[it] = make_float4(0.f, 0.f, 0.f, 0.f);
            else pw[it] = *(const float4*)(W + (size_t)rn * ldw + k0 + c4 * 4);
        }
    };
    auto storeS = [&]() {
        #pragma unroll
        for (int it = 0; it < 4; ++it) {
            int idx = it * 256 + tid;
            int row = idx >> 3, c4 = idx & 7;
            uint32_t off = (uint32_t)(row * 80 + c4 * 8);
            uint2 hp, lp;
            split4(pa[it], hp, lp);
            *(uint2*)(sm + 0*TILE_B + off) = hp;
            *(uint2*)(sm + 1*TILE_B + off) = lp;
            split4(pw[it], hp, lp);
            *(uint2*)(sm + 2*TILE_B + off) = hp;
            *(uint2*)(sm + 3*TILE_B + off) = lp;
        }
    };

    loadG(0);
    storeS();
    __syncthreads();

    for (int c = 0; c < NC; ++c) {
        if (c + 1 < NC) loadG((c + 1) << 5);
        #pragma unroll
        for (int ks = 0; ks < 2; ++ks) {
            #pragma unroll
            for (int pass = 0; pass < 3; ++pass) {
                int pA = (pass == 1) ? 1 : 0;      // Al only in pass 1
                int pW = (pass == 2) ? 3 : 2;      // Wl only in pass 2
                uint32_t af[4][4];
                #pragma unroll
                for (int i = 0; i < 4; ++i) {
                    uint32_t addr = smb + pA * TILE_B +
                        2u * (uint32_t)((a_row + i * 16) * 40 + a_col + ks * 16);
                    ldsm4(af[i], addr);
                }
                uint32_t bf[2][4];
                #pragma unroll
                for (int j = 0; j < 2; ++j) {
                    uint32_t addr = smb + pW * TILE_B +
                        2u * (uint32_t)((b_row + j * 16) * 40 + b_col + ks * 16);
                    ldsm4(bf[j], addr);
                }
                #pragma unroll
                for (int i = 0; i < 4; ++i)
                    #pragma unroll
                    for (int jt = 0; jt < 4; ++jt)
                        mma_bf16(acc[i][jt], af[i],
                                 bf[jt >> 1][(jt & 1) * 2], bf[jt >> 1][(jt & 1) * 2 + 1]);
            }
        }
        if (c + 1 < NC) {
            __syncthreads();
            storeS();
            __syncthreads();
        }
    }

    // epilogue
    #pragma unroll
    for (int i = 0; i < 4; ++i) {
        int r0 = bm + warp_m * 64 + i * 16 + (lane >> 2);
        #pragma unroll
        for (int jt = 0; jt < 4; ++jt) {
            int col = bn + warp_n * 32 + jt * 8 + (lane & 3) * 2;
            if (NGUARD && col >= N) continue;
            #pragma unroll
            for (int half = 0; half < 2; ++half) {
                int r = r0 + half * 8;
                float vx = acc[i][jt][half * 2 + 0];
                float vy = acc[i][jt][half * 2 + 1];
                if (BIAS) { vx += bias[col]; vy += bias[col + 1]; }
                float* cp = C + (size_t)r * ldc + col;
                if (ACC) {
                    float2 cc = *(float2*)cp;
                    vx += cc.x; vy += cc.y;
                }
                if (ACT == 1) { vx = softplusf(vx); vy = softplusf(vy); }
                float2 o; o.x = vx; o.y = vy;
                *(float2*)cp = o;
            }
        }
    }
}

// ---------------- embed -----------------------------------------------------
__global__ void embed_kernel(const int* __restrict__ ids,
                             const float* __restrict__ E,
                             float* __restrict__ x) {
    int i = blockIdx.x * blockDim.x + threadIdx.x;
    if (i >= MTOK * DM) return;
    int row = i >> 10;
    int d   = i & (DM - 1);
    x[i] = E[(size_t)ids[row] * DM + d];
}

// ---------------- layernorm -------------------------------------------------
__global__ __launch_bounds__(256) void ln_kernel(const float* __restrict__ x,
                                                 const float* __restrict__ w,
                                                 const float* __restrict__ b,
                                                 float* __restrict__ out) {
    int row = blockIdx.x;
    int tid = threadIdx.x;
    const float4* xr = (const float4*)(x + (size_t)row * DM);
    float4 v = xr[tid];
    float s  = v.x + v.y + v.z + v.w;
    float sq = v.x*v.x + v.y*v.y + v.z*v.z + v.w*v.w;
    #pragma unroll
    for (int o = 16; o > 0; o >>= 1) {
        s  += __shfl_xor_sync(0xffffffff, s,  o);
        sq += __shfl_xor_sync(0xffffffff, sq, o);
    }
    __shared__ float rs[8], rq[8];
    int warp = tid >> 5, lane = tid & 31;
    if (lane == 0) { rs[warp] = s; rq[warp] = sq; }
    __syncthreads();
    __shared__ float smu, srstd;
    if (tid == 0) {
        float ts = 0.f, tq = 0.f;
        #pragma unroll
        for (int i = 0; i < 8; ++i) { ts += rs[i]; tq += rq[i]; }
        float mu  = ts * (1.f / DM);
        float var = tq * (1.f / DM) - mu * mu;
        smu = mu;
        srstd = rsqrtf(var + 1e-5f);
    }
    __syncthreads();
    float mu = smu, rstd = srstd;
    float4 wv = ((const float4*)w)[tid];
    float4 bv = ((const float4*)b)[tid];
    float4 o;
    o.x = (v.x - mu) * rstd * wv.x + bv.x;
    o.y = (v.y - mu) * rstd * wv.y + bv.y;
    o.z = (v.z - mu) * rstd * wv.z + bv.z;
    o.w = (v.w - mu) * rstd * wv.w + bv.w;
    ((float4*)(out + (size_t)row * DM))[tid] = o;
}

// ---------------- causal depthwise conv (K=4) + silu ------------------------
__global__ void conv_silu_kernel(const float* __restrict__ xz,
                                 const float* __restrict__ cw,
                                 const float* __restrict__ cb,
                                 float* __restrict__ xc) {
    int i = blockIdx.x * blockDim.x + threadIdx.x;
    if (i >= MTOK * DI_) return;
    int c  = i & (DI_ - 1);
    int bt = i >> 11;
    int t  = bt & (T_ - 1);
    float acc = cb[c];
    #pragma unroll
    for (int k = 0; k < KK; ++k) {
        int tt = t + k - (KK - 1);
        if (tt >= 0)
            acc += xz[(size_t)(bt + k - (KK - 1)) * (2*DI_) + c] * cw[c*KK + k];
    }
    xc[i] = siluf(acc);
}

// ---------------- selective scan + D skip + silu(z) gate --------------------
__global__ __launch_bounds__(256) void scan_kernel(
    const float* __restrict__ xc,
    const float* __restrict__ dtb,
    const float* __restrict__ proj,
    const float* __restrict__ xz,
    const float* __restrict__ Alog,
    const float* __restrict__ Dp,
    float* __restrict__ y)
{
    int d = blockIdx.x * blockDim.x + threadIdx.x;
    int b = blockIdx.y;
    float A[NS];
    bool fast = true;
    #pragma unroll
    for (int n = 0; n < NS; ++n) {
        A[n] = -expf(Alog[(size_t)d * NS + n]);
        fast = fast && (fabsf(A[n] + (float)(n + 1)) <= 1e-3f * (n + 1));
    }
    float Dv = Dp[d];
    float h[NS];
    #pragma unroll
    for (int n = 0; n < NS; ++n) h[n] = 0.f;

    __shared__ float sBC[64][33];

    for (int t0 = 0; t0 < T_; t0 += 64) {
        __syncthreads();
        for (int e = threadIdx.x; e < 64*32; e += blockDim.x) {
            int i = e >> 5, j = e & 31;
            sBC[i][j] = proj[((size_t)b*T_ + t0 + i) * 96 + RR + j];
        }
        __syncthreads();
        for (int i = 0; i < 64; ++i) {
            size_t idx = (size_t)b*T_ + t0 + i;
            float u   = xc [idx * DI_ + d];
            float dtv = dtb[idx * DI_ + d];
            float dA[NS];
            if (fast) {
                float p  = __expf(-dtv);
                float p2 = p*p, p4 = p2*p2, p8 = p4*p4;
                dA[0]=p;        dA[1]=p2;       dA[2]=p2*p;      dA[3]=p4;
                dA[4]=p4*p;     dA[5]=p4*p2;    dA[6]=p4*p2*p;   dA[7]=p8;
                dA[8]=p8*p;     dA[9]=p8*p2;    dA[10]=p8*p2*p;  dA[11]=p8*p4;
                dA[12]=p8*p4*p; dA[13]=p8*p4*p2; dA[14]=p8*p4*p2*p; dA[15]=p8*p8;
            } else {
                #pragma unroll
                for (int n = 0; n < NS; ++n) dA[n] = __expf(dtv * A[n]);
            }
            float du = dtv * u;
            float accv = 0.f;
            #pragma unroll
            for (int n = 0; n < NS; ++n) {
                h[n] = dA[n] * h[n] + du * sBC[i][n];
                accv += h[n] * sBC[i][NS + n];
            }
            float z = xz[idx * (2*DI_) + DI_ + d];
            y[idx * DI_ + d] = (accv + u * Dv) * siluf(z);
        }
    }
}

// ---------------- launch ----------------------------------------------------
extern "C" void kernel_launch(void* const* d_in, const int* in_sizes, int n_in,
                              void* d_out, int out_size) {
    const int*   ids       = (const int*)  d_in[0];
    const float* embed_W   = (const float*)d_in[1];
    const float* out_b     = (const float*)d_in[2];
    const float* ln_w      = (const float*)d_in[3];
    const float* ln_b      = (const float*)d_in[4];
    const float* norm_w    = (const float*)d_in[5];
    const float* norm_b    = (const float*)d_in[6];
    const float* in_proj_W = (const float*)d_in[7];
    const float* conv_W    = (const float*)d_in[8];
    const float* conv_b    = (const float*)d_in[9];
    const float* x_proj_W  = (const float*)d_in[10];
    const float* dt_proj_W = (const float*)d_in[11];
    const float* dt_proj_b = (const float*)d_in[12];
    const float* A_log     = (const float*)d_in[13];
    const float* D_param   = (const float*)d_in[14];
    const float* out_projW = (const float*)d_in[15];
    float* out = (float*)d_out;

    float *px, *ph, *pxz, *pxc, *pproj, *pdt, *py;
    cudaGetSymbolAddress((void**)&px,    g_x);
    cudaGetSymbolAddress((void**)&ph,    g_h);
    cudaGetSymbolAddress((void**)&pxz,   g_xz);
    cudaGetSymbolAddress((void**)&pxc,   g_xc);
    cudaGetSymbolAddress((void**)&pproj, g_proj);
    cudaGetSymbolAddress((void**)&pdt,   g_dt);
    cudaGetSymbolAddress((void**)&py,    g_y);

    embed_kernel<<<(MTOK*DM + 255)/256, 256>>>(ids, embed_W, px);

    for (int l = 0; l < LL; ++l) {
        ln_kernel<<<MTOK, 256>>>(px, norm_w + l*DM, norm_b + l*DM, ph);

        // xz = h @ in_proj^T   (4096 x 4096 x 1024)
        gemm_hmma<0,false,false,false><<<dim3(32, 32), 256, GSMEM>>>(
            MTOK, 2*DI_, DM, ph, DM,
            in_proj_W + (size_t)l*2*DI_*DM, DM, pxz, 2*DI_, nullptr);

        conv_silu_kernel<<<(MTOK*DI_ + 255)/256, 256>>>(
            pxz, conv_W + (size_t)l*DI_*KK, conv_b + (size_t)l*DI_, pxc);

        // proj = xc @ x_proj^T  (4096 x 96 x 2048)
        gemm_hmma<0,false,false,true><<<dim3(32, 1), 256, GSMEM>>>(
            MTOK, 96, DI_, pxc, DI_,
            x_proj_W + (size_t)l*96*DI_, DI_, pproj, 96, nullptr);

        // dt = softplus(dt_r @ dt_proj^T + b)  (4096 x 2048 x 64)
        gemm_hmma<1,true,false,false><<<dim3(32, 16), 256, GSMEM>>>(
            MTOK, DI_, RR, pproj, 96,
            dt_proj_W + (size_t)l*DI_*RR, RR, pdt, DI_,
            dt_proj_b + (size_t)l*DI_);

        scan_kernel<<<dim3(DI_/256, B_), 256>>>(
            pxc, pdt, pproj, pxz,
            A_log + (size_t)l*DI_*NS, D_param + (size_t)l*DI_, py);

        // x += y @ out_proj^T   (4096 x 1024 x 2048), residual accumulate
        gemm_hmma<0,false,true,false><<<dim3(32, 8), 256, GSMEM>>>(
            MTOK, DM, DI_, py, DI_,
            out_projW + (size_t)l*DM*DI_, DI_, px, DM, nullptr);
    }

    ln_kernel<<<MTOK, 256>>>(px, ln_w, ln_b, ph);

    // logits = h @ embed^T + out_b   (4096 x 32000 x 1024)
    gemm_hmma<0,true,false,false><<<dim3(32, V_/128), 256, GSMEM>>>(
        MTOK, V_, DM, ph, DM, embed_W, DM, out, V_, out_b);
}